// round 6
// baseline (speedup 1.0000x reference)
#include <cuda_runtime.h>
#include <cuda_fp16.h>
#include <cstdint>
#include <math.h>

#define NS 2048      // speakers
#define NG 8         // utts per speaker
#define ND 128       // embed dim
#define NR (NS*NG)   // 16384 rows
#define KC 384       // K-concat: [Ah|Ah|Al] x [Bh|Bl|Bh]
#define NCH (KC/8)   // 48 16-byte chunks per row
#define BM 128
#define BN 64
#define NTILES (NS/BN)   // 32
#define NT 256           // threads per CTA

// ---------------------------------------------------------------------------
// device globals (no allocation allowed)
// ---------------------------------------------------------------------------
__device__ float g_lbl[NR];
__device__ __align__(16) __half2 g_A2[NR * (KC/2)];   // [row][192] pairs
__device__ __align__(16) __half2 g_B2[NS * (KC/2)];   // [spk][192] pairs

// ---------------------------------------------------------------------------
// PTX helpers (plain sm_80/90 — safe for compute_103)
// ---------------------------------------------------------------------------
__device__ __forceinline__ uint32_t smem_u32(const void* p) {
    uint32_t a;
    asm("{ .reg .u64 t; cvta.to.shared.u64 t, %1; cvt.u32.u64 %0, t; }" : "=r"(a) : "l"(p));
    return a;
}
#define CP16(dst32, gptr) \
    asm volatile("cp.async.cg.shared.global [%0], [%1], 16;" \
        :: "r"(dst32), "l"(__cvta_generic_to_global(gptr)) : "memory")
#define CP_COMMIT() asm volatile("cp.async.commit_group;" ::: "memory")
#define CP_WAIT0()  asm volatile("cp.async.wait_group 0;" ::: "memory")

__device__ __forceinline__ void ldsm4(unsigned r[4], uint32_t addr) {
    asm volatile("ldmatrix.sync.aligned.m8n8.x4.shared.b16 {%0,%1,%2,%3}, [%4];"
        : "=r"(r[0]), "=r"(r[1]), "=r"(r[2]), "=r"(r[3]) : "r"(addr));
}
__device__ __forceinline__ void mma16816(float d[4], const unsigned a[4],
                                         unsigned b0, unsigned b1) {
    asm volatile("mma.sync.aligned.m16n8k16.row.col.f32.f16.f16.f32 "
        "{%0,%1,%2,%3}, {%4,%5,%6,%7}, {%8,%9}, {%0,%1,%2,%3};"
        : "+f"(d[0]), "+f"(d[1]), "+f"(d[2]), "+f"(d[3])
        : "r"(a[0]), "r"(a[1]), "r"(a[2]), "r"(a[3]), "r"(b0), "r"(b1));
}

// ---------------------------------------------------------------------------
// Kernel 1: per-speaker prep (off the critical path)
// ---------------------------------------------------------------------------
__device__ __forceinline__ void reduce8(const float v[NG], float (*scr)[4],
                                        float* out8, int lane, int warp, int tid) {
    #pragma unroll
    for (int g = 0; g < NG; g++) {
        float r = v[g];
        #pragma unroll
        for (int off = 16; off > 0; off >>= 1)
            r += __shfl_xor_sync(0xffffffffu, r, off);
        if (lane == 0) scr[g][warp] = r;
    }
    __syncthreads();
    if (tid < NG) out8[tid] = scr[tid][0] + scr[tid][1] + scr[tid][2] + scr[tid][3];
    __syncthreads();
}

__device__ __forceinline__ __half2 hi_pair(float a, float b) {
    return __halves2half2(__float2half_rn(a), __float2half_rn(b));
}
__device__ __forceinline__ __half2 lo_pair(float a, float b) {
    float ra = a - __half2float(__float2half_rn(a));
    float rb = b - __half2float(__float2half_rn(b));
    return __halves2half2(__float2half_rn(ra), __float2half_rn(rb));
}

__global__ void prep_kernel(const float* __restrict__ x, float* __restrict__ out) {
    __shared__ float scr[NG][4];
    __shared__ float out8[NG];
    __shared__ float cnorm2;
    __shared__ float xs[NG][ND];
    __shared__ float cs[ND];

    const int s    = blockIdx.x;
    const int j    = threadIdx.x;       // 0..127
    const int lane = j & 31;
    const int warp = j >> 5;

    float xg[NG];
    #pragma unroll
    for (int g = 0; g < NG; g++) xg[g] = x[(s * NG + g) * ND + j];

    float v[NG];
    #pragma unroll
    for (int g = 0; g < NG; g++) v[g] = xg[g] * xg[g];
    reduce8(v, scr, out8, lane, warp, j);
    float xn[NG];
    float sum = 0.f;
    #pragma unroll
    for (int g = 0; g < NG; g++) {
        float nrm = fmaxf(sqrtf(out8[g]), 1e-12f);
        xn[g] = xg[g] / nrm;
        sum += xn[g];
    }

    float cent = sum * 0.125f;
    {
        float c2 = cent * cent;
        #pragma unroll
        for (int off = 16; off > 0; off >>= 1)
            c2 += __shfl_xor_sync(0xffffffffu, c2, off);
        if (lane == 0) scr[0][warp] = c2;
        __syncthreads();
        if (j == 0) cnorm2 = scr[0][0] + scr[0][1] + scr[0][2] + scr[0][3];
        __syncthreads();
    }
    float centv = 30.f * cent / fmaxf(sqrtf(cnorm2), 1e-8f);

    float exc[NG];
    #pragma unroll
    for (int g = 0; g < NG; g++) {
        exc[g] = (sum - xn[g]) * (1.0f / 7.0f);
        v[g] = exc[g] * exc[g];
    }
    reduce8(v, scr, out8, lane, warp, j);
    float e2[NG];
    #pragma unroll
    for (int g = 0; g < NG; g++) e2[g] = out8[g];
    #pragma unroll
    for (int g = 0; g < NG; g++)
        v[g] = xn[g] * exc[g] / fmaxf(sqrtf(e2[g]), 1e-8f);
    reduce8(v, scr, out8, lane, warp, j);
    if (j < NG) g_lbl[s * NG + j] = fmaxf(30.f * out8[j], 1e-6f);

    #pragma unroll
    for (int g = 0; g < NG; g++) xs[g][j] = xn[g];
    cs[j] = centv;
    __syncthreads();

    // A': [Ah | Ah | Al] fp16 pairs
    const int abase = s * NG * (KC/2);
    #pragma unroll
    for (int it = 0; it < (NG * (KC/2)) / 128; it++) {
        int idx = it * 128 + j;
        int r  = idx / (KC/2);
        int p  = idx % (KC/2);
        int pm = p & 63, blk = p >> 6;
        float v0 = xs[r][2*pm], v1 = xs[r][2*pm+1];
        g_A2[abase + idx] = (blk < 2) ? hi_pair(v0, v1) : lo_pair(v0, v1);
    }

    // B': [Bh | Bl | Bh]
    #pragma unroll
    for (int p = j; p < (KC/2); p += 128) {
        int pm = p & 63, blk = p >> 6;
        float v0 = cs[2*pm], v1 = cs[2*pm+1];
        g_B2[s * (KC/2) + p] = (blk == 1) ? lo_pair(v0, v1) : hi_pair(v0, v1);
    }

    if (s == 0 && j == 0) out[0] = 0.f;   // zero accumulator (d_out is poisoned)
}

// ---------------------------------------------------------------------------
// Kernel 2: HMMA GEMM (fp16x3) + fused online log-softmax.
// 128 CTAs x 256 threads. One barrier per tile; the exp epilogue of tile t-1
// is interleaved into the mma loop of tile t (deferred via accPrev).
// ---------------------------------------------------------------------------
#define SM_A     0
#define SM_B0    98304
#define SM_B1    147456
#define SM_TOTAL 196608

__global__ void __launch_bounds__(NT, 1) gemm_kernel(float* __restrict__ out) {
    extern __shared__ char smem[];
    __shared__ float zbuf[BM][2];
    __shared__ float cbuf[BM][2];
    __shared__ float red[8];

    const uint32_t sb = smem_u32(smem);
    const int tid  = threadIdx.x;
    const int lane = tid & 31;
    const int wid  = tid >> 5;
    const int wm   = wid & 3;        // 0..3  (32-row slices)
    const int wn   = wid >> 2;       // 0..1  (32-col slices)
    const int br0  = blockIdx.x * BM;
    const int td   = blockIdx.x >> 2;   // B tile holding this block's diagonal

    const char* gA = (const char*)g_A2;
    const char* gB = (const char*)g_B2;

    // ---- prologue: A tile + B tile 0 (one cp.async group) ----
    #pragma unroll
    for (int ii = 0; ii < (BM * NCH) / NT; ii++) {     // 24 iters
        int idx = ii * NT + tid;
        int c = idx % NCH, r = idx / NCH;
        CP16(sb + SM_A + r * 768 + ((c ^ (r & 7)) << 4),
             gA + (size_t)(br0 + r) * 768 + c * 16);
    }
    #pragma unroll
    for (int ii = 0; ii < (BN * NCH) / NT; ii++) {     // 6 iters
        int idx = ii * NT + tid;
        int c = idx % NCH, n = idx / NCH;
        CP16(sb + SM_B0 + n * 768 + ((c ^ (n & 7)) << 4),
             gB + (size_t)n * 768 + c * 16);
    }
    CP_COMMIT();

    // ---- per-thread fragment address bases ----
    uint32_t aBase[2], aS[2];
    #pragma unroll
    for (int mi = 0; mi < 2; mi++) {
        int row = wm * 32 + mi * 16 + (lane & 15);
        aBase[mi] = sb + SM_A + row * 768;
        aS[mi] = row & 7;
    }
    const uint32_t cbA = (lane >> 4);          // k-octet within k16
    uint32_t bOff[2], bS[2];
    #pragma unroll
    for (int j2 = 0; j2 < 2; j2++) {
        int n = wn * 32 + j2 * 16 + ((lane >> 4) & 1) * 8 + (lane & 7);
        bOff[j2] = n * 768;
        bS[j2] = n & 7;
    }
    const uint32_t cbB = (lane >> 3) & 1;

    // row slots: slot = mi*2 + h, row = wm*32 + mi*16 + h*8 + lane/4
    int rl[4], dc[4];
    float zsum[4], zcorr[4];
    #pragma unroll
    for (int sl = 0; sl < 4; sl++) {
        int mi = sl >> 1, h = sl & 1;
        rl[sl] = wm * 32 + mi * 16 + h * 8 + (lane >> 2);
        dc[sl] = (br0 + rl[sl]) >> 3;
        zsum[sl] = 0.f; zcorr[sl] = 0.f;
    }

    const uint32_t bufB[2] = { sb + SM_B0, sb + SM_B1 };
    const int colBase = wn * 32 + (lane & 3) * 2;

    float acc[2][4][4], accPrev[2][4][4];

    for (int t = 0; t < NTILES; t++) {
        CP_WAIT0();
        __syncthreads();   // all warps: B(t) ready AND done reading buf[(t+1)&1]

        // prefetch B(t+1) into the buffer mma(t-1) just released
        if (t + 1 < NTILES) {
            const uint32_t bb = bufB[(t + 1) & 1];
            #pragma unroll
            for (int ii = 0; ii < (BN * NCH) / NT; ii++) {
                int idx = ii * NT + tid;
                int c = idx % NCH, n = idx / NCH;
                CP16(bb + n * 768 + ((c ^ (n & 7)) << 4),
                     gB + (size_t)((t + 1) * BN + n) * 768 + c * 16);
            }
            CP_COMMIT();
        }

        const uint32_t bcur = bufB[t & 1];
        #pragma unroll
        for (int mi = 0; mi < 2; mi++)
            #pragma unroll
            for (int nj = 0; nj < 4; nj++)
                #pragma unroll
                for (int q = 0; q < 4; q++) acc[mi][nj][q] = 0.f;

        const bool havePrev = (t > 0);
        const int  tt = t - 1;
        const bool isDiag = (tt == td);

        #pragma unroll
        for (int ks = 0; ks < KC / 16; ks++) {          // 24 steps
            const uint32_t c2 = 2u * ks;
            unsigned af[2][4], bf[2][4];
            #pragma unroll
            for (int mi = 0; mi < 2; mi++)
                ldsm4(af[mi], aBase[mi] + (((c2 | cbA) ^ aS[mi]) << 4));
            #pragma unroll
            for (int j2 = 0; j2 < 2; j2++)
                ldsm4(bf[j2], bcur + bOff[j2] + (((c2 | cbB) ^ bS[j2]) << 4));
            #pragma unroll
            for (int mi = 0; mi < 2; mi++)
                #pragma unroll
                for (int nj = 0; nj < 4; nj++)
                    mma16816(acc[mi][nj], af[mi],
                             bf[nj >> 1][(nj & 1) * 2], bf[nj >> 1][(nj & 1) * 2 + 1]);

            // deferred epilogue of tile t-1, one group per early k-step
            if (ks < 8 && havePrev) {
                const int mi = ks >> 2, nj = ks & 3;
                const float* a = accPrev[mi][nj];
                float e0 = __expf(fmaxf(a[0], 1e-6f) - 30.f);
                float e1 = __expf(fmaxf(a[1], 1e-6f) - 30.f);
                float e2 = __expf(fmaxf(a[2], 1e-6f) - 30.f);
                float e3 = __expf(fmaxf(a[3], 1e-6f) - 30.f);
                zsum[mi*2]   += e0 + e1;
                zsum[mi*2+1] += e2 + e3;
                if (isDiag) {
                    int cb = tt * BN + nj * 8 + colBase;
                    if (cb     == dc[mi*2])   zcorr[mi*2]   += e0;
                    if (cb + 1 == dc[mi*2])   zcorr[mi*2]   += e1;
                    if (cb     == dc[mi*2+1]) zcorr[mi*2+1] += e2;
                    if (cb + 1 == dc[mi*2+1]) zcorr[mi*2+1] += e3;
                }
            }
        }

        // stash results for the deferred epilogue
        #pragma unroll
        for (int mi = 0; mi < 2; mi++)
            #pragma unroll
            for (int nj = 0; nj < 4; nj++)
                #pragma unroll
                for (int q = 0; q < 4; q++) accPrev[mi][nj][q] = acc[mi][nj][q];
    }

    // tail epilogue: tile NTILES-1
    {
        const int tt = NTILES - 1;
        const bool isDiag = (tt == td);
        #pragma unroll
        for (int g = 0; g < 8; g++) {
            const int mi = g >> 2, nj = g & 3;
            const float* a = accPrev[mi][nj];
            float e0 = __expf(fmaxf(a[0], 1e-6f) - 30.f);
            float e1 = __expf(fmaxf(a[1], 1e-6f) - 30.f);
            float e2 = __expf(fmaxf(a[2], 1e-6f) - 30.f);
            float e3 = __expf(fmaxf(a[3], 1e-6f) - 30.f);
            zsum[mi*2]   += e0 + e1;
            zsum[mi*2+1] += e2 + e3;
            if (isDiag) {
                int cb = tt * BN + nj * 8 + colBase;
                if (cb     == dc[mi*2])   zcorr[mi*2]   += e0;
                if (cb + 1 == dc[mi*2])   zcorr[mi*2]   += e1;
                if (cb     == dc[mi*2+1]) zcorr[mi*2+1] += e2;
                if (cb + 1 == dc[mi*2+1]) zcorr[mi*2+1] += e3;
            }
        }
    }

    // reduce z across the 4 lanes of each quad (same row)
    #pragma unroll
    for (int sl = 0; sl < 4; sl++) {
        float z = zsum[sl], c = zcorr[sl];
        z += __shfl_xor_sync(0xffffffffu, z, 1);
        z += __shfl_xor_sync(0xffffffffu, z, 2);
        c += __shfl_xor_sync(0xffffffffu, c, 1);
        c += __shfl_xor_sync(0xffffffffu, c, 2);
        if ((lane & 3) == 0) { zbuf[rl[sl]][wn] = z; cbuf[rl[sl]][wn] = c; }
    }
    __syncthreads();

    // per-row loss + block reduce + single atomicAdd
    float loss = 0.f;
    if (tid < BM) {
        int row = br0 + tid;
        float lbl = g_lbl[row];
        float Z = zbuf[tid][0] + zbuf[tid][1] - cbuf[tid][0] - cbuf[tid][1]
                  + __expf(lbl - 30.f);
        loss = 30.f + logf(Z) - lbl;
    }
    #pragma unroll
    for (int off = 16; off > 0; off >>= 1)
        loss += __shfl_xor_sync(0xffffffffu, loss, off);
    if (lane == 0) red[wid] = loss;
    __syncthreads();
    if (tid == 0) {
        float tot = 0.f;
        #pragma unroll
        for (int q = 0; q < 8; q++) tot += red[q];
        atomicAdd(out, tot * (1.f / (float)NR));
    }
}

// ---------------------------------------------------------------------------
extern "C" void kernel_launch(void* const* d_in, const int* in_sizes, int n_in,
                              void* d_out, int out_size) {
    const float* x = (const float*)d_in[0];
    float* out = (float*)d_out;

    prep_kernel<<<NS, 128>>>(x, out);

    cudaFuncSetAttribute(gemm_kernel, cudaFuncAttributeMaxDynamicSharedMemorySize, SM_TOTAL);
    gemm_kernel<<<NR / BM, NT, SM_TOTAL>>>(out);
}

// round 7
// speedup vs baseline: 1.2996x; 1.2996x over previous
#include <cuda_runtime.h>
#include <cuda_fp16.h>
#include <cstdint>
#include <math.h>

#define NS 2048      // speakers
#define NG 8         // utts per speaker
#define ND 128       // embed dim
#define NR (NS*NG)   // 16384 rows
#define KC 256       // 2-term K-concat: [Ah|Al] x [Bh|Bh]  (= A·Bh exactly)
#define NCH (KC/8)   // 32 16-byte chunks per row
#define ROWB (KC*2)  // 512 bytes per row
#define BM 128
#define BN 64
#define NTILES (NS/BN)   // 32
#define NT 256           // threads per CTA

// ---------------------------------------------------------------------------
// device globals (no allocation allowed)
// ---------------------------------------------------------------------------
__device__ float g_lbl[NR];
__device__ __align__(16) __half2 g_A2[NR * (KC/2)];   // [row][128] pairs
__device__ __align__(16) __half2 g_B2[NS * (KC/2)];   // [spk][128] pairs

// ---------------------------------------------------------------------------
// PTX helpers (plain sm_80/90 — safe for compute_103)
// ---------------------------------------------------------------------------
__device__ __forceinline__ uint32_t smem_u32(const void* p) {
    uint32_t a;
    asm("{ .reg .u64 t; cvta.to.shared.u64 t, %1; cvt.u32.u64 %0, t; }" : "=r"(a) : "l"(p));
    return a;
}
#define CP16(dst32, gptr) \
    asm volatile("cp.async.cg.shared.global [%0], [%1], 16;" \
        :: "r"(dst32), "l"(__cvta_generic_to_global(gptr)) : "memory")
#define CP_COMMIT() asm volatile("cp.async.commit_group;" ::: "memory")
#define CP_WAIT0()  asm volatile("cp.async.wait_group 0;" ::: "memory")
#define CP_WAIT1()  asm volatile("cp.async.wait_group 1;" ::: "memory")

__device__ __forceinline__ void ldsm4(unsigned r[4], uint32_t addr) {
    asm volatile("ldmatrix.sync.aligned.m8n8.x4.shared.b16 {%0,%1,%2,%3}, [%4];"
        : "=r"(r[0]), "=r"(r[1]), "=r"(r[2]), "=r"(r[3]) : "r"(addr));
}
__device__ __forceinline__ void mma16816(float d[4], const unsigned a[4],
                                         unsigned b0, unsigned b1) {
    asm volatile("mma.sync.aligned.m16n8k16.row.col.f32.f16.f16.f32 "
        "{%0,%1,%2,%3}, {%4,%5,%6,%7}, {%8,%9}, {%0,%1,%2,%3};"
        : "+f"(d[0]), "+f"(d[1]), "+f"(d[2]), "+f"(d[3])
        : "r"(a[0]), "r"(a[1]), "r"(a[2]), "r"(a[3]), "r"(b0), "r"(b1));
}

// ---------------------------------------------------------------------------
// Kernel 1: per-speaker prep (off the critical path)
// ---------------------------------------------------------------------------
__device__ __forceinline__ void reduce8(const float v[NG], float (*scr)[4],
                                        float* out8, int lane, int warp, int tid) {
    #pragma unroll
    for (int g = 0; g < NG; g++) {
        float r = v[g];
        #pragma unroll
        for (int off = 16; off > 0; off >>= 1)
            r += __shfl_xor_sync(0xffffffffu, r, off);
        if (lane == 0) scr[g][warp] = r;
    }
    __syncthreads();
    if (tid < NG) out8[tid] = scr[tid][0] + scr[tid][1] + scr[tid][2] + scr[tid][3];
    __syncthreads();
}

__device__ __forceinline__ __half2 hi_pair(float a, float b) {
    return __halves2half2(__float2half_rn(a), __float2half_rn(b));
}
__device__ __forceinline__ __half2 lo_pair(float a, float b) {
    float ra = a - __half2float(__float2half_rn(a));
    float rb = b - __half2float(__float2half_rn(b));
    return __halves2half2(__float2half_rn(ra), __float2half_rn(rb));
}

__global__ void prep_kernel(const float* __restrict__ x, float* __restrict__ out) {
    __shared__ float scr[NG][4];
    __shared__ float out8[NG];
    __shared__ float cnorm2;
    __shared__ float xs[NG][ND];
    __shared__ float cs[ND];

    const int s    = blockIdx.x;
    const int j    = threadIdx.x;       // 0..127
    const int lane = j & 31;
    const int warp = j >> 5;

    float xg[NG];
    #pragma unroll
    for (int g = 0; g < NG; g++) xg[g] = x[(s * NG + g) * ND + j];

    float v[NG];
    #pragma unroll
    for (int g = 0; g < NG; g++) v[g] = xg[g] * xg[g];
    reduce8(v, scr, out8, lane, warp, j);
    float xn[NG];
    float sum = 0.f;
    #pragma unroll
    for (int g = 0; g < NG; g++) {
        float nrm = fmaxf(sqrtf(out8[g]), 1e-12f);
        xn[g] = xg[g] / nrm;
        sum += xn[g];
    }

    float cent = sum * 0.125f;
    {
        float c2 = cent * cent;
        #pragma unroll
        for (int off = 16; off > 0; off >>= 1)
            c2 += __shfl_xor_sync(0xffffffffu, c2, off);
        if (lane == 0) scr[0][warp] = c2;
        __syncthreads();
        if (j == 0) cnorm2 = scr[0][0] + scr[0][1] + scr[0][2] + scr[0][3];
        __syncthreads();
    }
    float centv = 30.f * cent / fmaxf(sqrtf(cnorm2), 1e-8f);

    float exc[NG];
    #pragma unroll
    for (int g = 0; g < NG; g++) {
        exc[g] = (sum - xn[g]) * (1.0f / 7.0f);
        v[g] = exc[g] * exc[g];
    }
    reduce8(v, scr, out8, lane, warp, j);
    float e2[NG];
    #pragma unroll
    for (int g = 0; g < NG; g++) e2[g] = out8[g];
    #pragma unroll
    for (int g = 0; g < NG; g++)
        v[g] = xn[g] * exc[g] / fmaxf(sqrtf(e2[g]), 1e-8f);
    reduce8(v, scr, out8, lane, warp, j);
    if (j < NG) g_lbl[s * NG + j] = fmaxf(30.f * out8[j], 1e-6f);

    #pragma unroll
    for (int g = 0; g < NG; g++) xs[g][j] = xn[g];
    cs[j] = centv;
    __syncthreads();

    // A': [Ah(128) | Al(128)] fp16 pairs
    const int abase = s * NG * (KC/2);
    #pragma unroll
    for (int it = 0; it < (NG * (KC/2)) / 128; it++) {   // 8 iters
        int idx = it * 128 + j;
        int r  = idx / (KC/2);
        int p  = idx % (KC/2);
        int pm = p & 63, blk = p >> 6;
        float v0 = xs[r][2*pm], v1 = xs[r][2*pm+1];
        g_A2[abase + idx] = (blk == 0) ? hi_pair(v0, v1) : lo_pair(v0, v1);
    }

    // B': [Bh | Bh]
    #pragma unroll
    for (int p = j; p < (KC/2); p += 128) {
        int pm = p & 63;
        g_B2[s * (KC/2) + p] = hi_pair(cs[2*pm], cs[2*pm+1]);
    }

    if (s == 0 && j == 0) out[0] = 0.f;   // zero accumulator (d_out is poisoned)
}

// ---------------------------------------------------------------------------
// Kernel 2: HMMA GEMM (fp16 2-term) + fused online log-softmax.
// 128 CTAs x 256 threads (8 warps). CTA = 128 rows x all 2048 cols.
// A (128x256 fp16) smem-resident; B in 64-col double-buffered tiles.
// Warp grid 4m x 2n, warp tile 32x32.
// ---------------------------------------------------------------------------
#define SM_A     0
#define SM_B0    (BM * ROWB)               // 65536
#define SM_B1    (SM_B0 + BN * ROWB)       // 98304
#define SM_TOTAL (SM_B1 + BN * ROWB)       // 131072

__global__ void __launch_bounds__(NT, 1) gemm_kernel(float* __restrict__ out) {
    extern __shared__ char smem[];
    __shared__ float zbuf[BM][2];
    __shared__ float cbuf[BM][2];
    __shared__ float red[8];

    const uint32_t sb = smem_u32(smem);
    const int tid  = threadIdx.x;
    const int lane = tid & 31;
    const int wid  = tid >> 5;
    const int wm   = wid & 3;        // 0..3  (32-row slices)
    const int wn   = wid >> 2;       // 0..1  (32-col slices)
    const int br0  = blockIdx.x * BM;
    const int td   = blockIdx.x >> 2;   // B tile holding this block's diagonal

    const char* gA = (const char*)g_A2;
    const char* gB = (const char*)g_B2;

    // ---- prologue: A tile + B tile 0 ----
    #pragma unroll
    for (int ii = 0; ii < (BM * NCH) / NT; ii++) {     // 16 iters
        int idx = ii * NT + tid;
        int c = idx % NCH, r = idx / NCH;
        CP16(sb + SM_A + r * ROWB + ((c ^ (r & 7)) << 4),
             gA + (size_t)(br0 + r) * ROWB + c * 16);
    }
    #pragma unroll
    for (int ii = 0; ii < (BN * NCH) / NT; ii++) {     // 8 iters
        int idx = ii * NT + tid;
        int c = idx % NCH, n = idx / NCH;
        CP16(sb + SM_B0 + n * ROWB + ((c ^ (n & 7)) << 4),
             gB + (size_t)n * ROWB + c * 16);
    }
    CP_COMMIT();

    // ---- per-thread fragment address bases ----
    uint32_t aBase[2], aS[2];
    #pragma unroll
    for (int mi = 0; mi < 2; mi++) {
        int row = wm * 32 + mi * 16 + (lane & 15);
        aBase[mi] = sb + SM_A + row * ROWB;
        aS[mi] = row & 7;
    }
    const uint32_t cbA = (lane >> 4);          // k-octet within k16
    uint32_t bOff[2], bS[2];
    #pragma unroll
    for (int j2 = 0; j2 < 2; j2++) {
        int n = wn * 32 + j2 * 16 + ((lane >> 4) & 1) * 8 + (lane & 7);
        bOff[j2] = n * ROWB;
        bS[j2] = n & 7;
    }
    const uint32_t cbB = (lane >> 3) & 1;

    // row slots: slot = mi*2 + h, row = wm*32 + mi*16 + h*8 + lane/4
    int rl[4], dc[4];
    float zsum[4], zcorr[4];
    #pragma unroll
    for (int sl = 0; sl < 4; sl++) {
        int mi = sl >> 1, h = sl & 1;
        rl[sl] = wm * 32 + mi * 16 + h * 8 + (lane >> 2);
        dc[sl] = (br0 + rl[sl]) >> 3;
        zsum[sl] = 0.f; zcorr[sl] = 0.f;
    }

    const uint32_t bufB[2] = { sb + SM_B0, sb + SM_B1 };

    for (int t = 0; t < NTILES; t++) {
        if (t + 1 < NTILES) {
            const uint32_t bb = bufB[(t + 1) & 1];
            #pragma unroll
            for (int ii = 0; ii < (BN * NCH) / NT; ii++) {
                int idx = ii * NT + tid;
                int c = idx % NCH, n = idx / NCH;
                CP16(bb + n * ROWB + ((c ^ (n & 7)) << 4),
                     gB + (size_t)((t + 1) * BN + n) * ROWB + c * 16);
            }
            CP_COMMIT();
            CP_WAIT1();
        } else {
            CP_WAIT0();
        }
        __syncthreads();

        const uint32_t bcur = bufB[t & 1];
        float acc[2][4][4];
        #pragma unroll
        for (int mi = 0; mi < 2; mi++)
            #pragma unroll
            for (int nj = 0; nj < 4; nj++)
                #pragma unroll
                for (int q = 0; q < 4; q++) acc[mi][nj][q] = 0.f;

        #pragma unroll
        for (int ks = 0; ks < KC / 16; ks++) {          // 16 steps
            const uint32_t c2 = 2u * ks;
            unsigned af[2][4], bf[2][4];
            #pragma unroll
            for (int mi = 0; mi < 2; mi++)
                ldsm4(af[mi], aBase[mi] + (((c2 | cbA) ^ aS[mi]) << 4));
            #pragma unroll
            for (int j2 = 0; j2 < 2; j2++)
                ldsm4(bf[j2], bcur + bOff[j2] + (((c2 | cbB) ^ bS[j2]) << 4));
            #pragma unroll
            for (int mi = 0; mi < 2; mi++)
                #pragma unroll
                for (int nj = 0; nj < 4; nj++)
                    mma16816(acc[mi][nj], af[mi],
                             bf[nj >> 1][(nj & 1) * 2], bf[nj >> 1][(nj & 1) * 2 + 1]);
        }

        // fused epilogue: clamp + exp + online Z (logits <= 30, no max pass)
        if (t == td) {
            #pragma unroll
            for (int mi = 0; mi < 2; mi++)
                #pragma unroll
                for (int nj = 0; nj < 4; nj++) {
                    int cb = t * BN + wn * 32 + nj * 8 + (lane & 3) * 2;
                    float e0 = __expf(fmaxf(acc[mi][nj][0], 1e-6f) - 30.f);
                    float e1 = __expf(fmaxf(acc[mi][nj][1], 1e-6f) - 30.f);
                    float e2 = __expf(fmaxf(acc[mi][nj][2], 1e-6f) - 30.f);
                    float e3 = __expf(fmaxf(acc[mi][nj][3], 1e-6f) - 30.f);
                    zsum[mi*2]   += e0 + e1;
                    zsum[mi*2+1] += e2 + e3;
                    if (cb     == dc[mi*2])   zcorr[mi*2]   += e0;
                    if (cb + 1 == dc[mi*2])   zcorr[mi*2]   += e1;
                    if (cb     == dc[mi*2+1]) zcorr[mi*2+1] += e2;
                    if (cb + 1 == dc[mi*2+1]) zcorr[mi*2+1] += e3;
                }
        } else {
            #pragma unroll
            for (int mi = 0; mi < 2; mi++)
                #pragma unroll
                for (int nj = 0; nj < 4; nj++) {
                    float e0 = __expf(fmaxf(acc[mi][nj][0], 1e-6f) - 30.f);
                    float e1 = __expf(fmaxf(acc[mi][nj][1], 1e-6f) - 30.f);
                    float e2 = __expf(fmaxf(acc[mi][nj][2], 1e-6f) - 30.f);
                    float e3 = __expf(fmaxf(acc[mi][nj][3], 1e-6f) - 30.f);
                    zsum[mi*2]   += e0 + e1;
                    zsum[mi*2+1] += e2 + e3;
                }
        }
        __syncthreads();
    }

    // reduce z across the 4 lanes of each quad (same row)
    #pragma unroll
    for (int sl = 0; sl < 4; sl++) {
        float z = zsum[sl], c = zcorr[sl];
        z += __shfl_xor_sync(0xffffffffu, z, 1);
        z += __shfl_xor_sync(0xffffffffu, z, 2);
        c += __shfl_xor_sync(0xffffffffu, c, 1);
        c += __shfl_xor_sync(0xffffffffu, c, 2);
        if ((lane & 3) == 0) { zbuf[rl[sl]][wn] = z; cbuf[rl[sl]][wn] = c; }
    }
    __syncthreads();

    // per-row loss + block reduce + single atomicAdd
    float loss = 0.f;
    if (tid < BM) {
        int row = br0 + tid;
        float lbl = g_lbl[row];
        float Z = zbuf[tid][0] + zbuf[tid][1] - cbuf[tid][0] - cbuf[tid][1]
                  + __expf(lbl - 30.f);
        loss = 30.f + logf(Z) - lbl;
    }
    #pragma unroll
    for (int off = 16; off > 0; off >>= 1)
        loss += __shfl_xor_sync(0xffffffffu, loss, off);
    if (lane == 0) red[wid] = loss;
    __syncthreads();
    if (tid == 0) {
        float tot = 0.f;
        #pragma unroll
        for (int q = 0; q < 8; q++) tot += red[q];
        atomicAdd(out, tot * (1.f / (float)NR));
    }
}

// ---------------------------------------------------------------------------
extern "C" void kernel_launch(void* const* d_in, const int* in_sizes, int n_in,
                              void* d_out, int out_size) {
    const float* x = (const float*)d_in[0];
    float* out = (float*)d_out;

    prep_kernel<<<NS, 128>>>(x, out);

    cudaFuncSetAttribute(gemm_kernel, cudaFuncAttributeMaxDynamicSharedMemorySize, SM_TOTAL);
    gemm_kernel<<<NR / BM, NT, SM_TOTAL>>>(out);
}

// round 8
// speedup vs baseline: 1.3734x; 1.0568x over previous
#include <cuda_runtime.h>
#include <cuda_fp16.h>
#include <cstdint>
#include <math.h>

#define NS 2048      // speakers
#define NG 8         // utts per speaker
#define ND 128       // embed dim
#define NR (NS*NG)   // 16384 rows
#define KC 256       // 2-term K-concat: [Ah|Al] x [Bh|Bh]  (= A·Bh exactly)
#define NCH (KC/8)   // 32 16-byte chunks per row
#define ROWB (KC*2)  // 512 bytes per row
#define BM 128
#define BN 64
#define NTILES (NS/BN)   // 32
#define NT 256           // threads per CTA
#define NKS (KC/16)      // 16 k-steps

// ---------------------------------------------------------------------------
// device globals (no allocation allowed)
// ---------------------------------------------------------------------------
__device__ float g_lbl[NR];
__device__ __align__(16) __half2 g_A2[NR * (KC/2)];   // [row][128] pairs
__device__ __align__(16) __half2 g_B2[NS * (KC/2)];   // [spk][128] pairs

// ---------------------------------------------------------------------------
// PTX helpers (plain sm_80/90 — safe for compute_103)
// ---------------------------------------------------------------------------
__device__ __forceinline__ uint32_t smem_u32(const void* p) {
    uint32_t a;
    asm("{ .reg .u64 t; cvta.to.shared.u64 t, %1; cvt.u32.u64 %0, t; }" : "=r"(a) : "l"(p));
    return a;
}
#define CP16(dst32, gptr) \
    asm volatile("cp.async.cg.shared.global [%0], [%1], 16;" \
        :: "r"(dst32), "l"(__cvta_generic_to_global(gptr)) : "memory")
#define CP_COMMIT() asm volatile("cp.async.commit_group;" ::: "memory")
#define CP_WAIT0()  asm volatile("cp.async.wait_group 0;" ::: "memory")

__device__ __forceinline__ void ldsm4(unsigned r[4], uint32_t addr) {
    asm volatile("ldmatrix.sync.aligned.m8n8.x4.shared.b16 {%0,%1,%2,%3}, [%4];"
        : "=r"(r[0]), "=r"(r[1]), "=r"(r[2]), "=r"(r[3]) : "r"(addr));
}
__device__ __forceinline__ void mma16816(float d[4], const unsigned a[4],
                                         unsigned b0, unsigned b1) {
    asm volatile("mma.sync.aligned.m16n8k16.row.col.f32.f16.f16.f32 "
        "{%0,%1,%2,%3}, {%4,%5,%6,%7}, {%8,%9}, {%0,%1,%2,%3};"
        : "+f"(d[0]), "+f"(d[1]), "+f"(d[2]), "+f"(d[3])
        : "r"(a[0]), "r"(a[1]), "r"(a[2]), "r"(a[3]), "r"(b0), "r"(b1));
}

// ---------------------------------------------------------------------------
// Kernel 1: per-speaker prep (off the critical path)
// ---------------------------------------------------------------------------
__device__ __forceinline__ void reduce8(const float v[NG], float (*scr)[4],
                                        float* out8, int lane, int warp, int tid) {
    #pragma unroll
    for (int g = 0; g < NG; g++) {
        float r = v[g];
        #pragma unroll
        for (int off = 16; off > 0; off >>= 1)
            r += __shfl_xor_sync(0xffffffffu, r, off);
        if (lane == 0) scr[g][warp] = r;
    }
    __syncthreads();
    if (tid < NG) out8[tid] = scr[tid][0] + scr[tid][1] + scr[tid][2] + scr[tid][3];
    __syncthreads();
}

__device__ __forceinline__ __half2 hi_pair(float a, float b) {
    return __halves2half2(__float2half_rn(a), __float2half_rn(b));
}
__device__ __forceinline__ __half2 lo_pair(float a, float b) {
    float ra = a - __half2float(__float2half_rn(a));
    float rb = b - __half2float(__float2half_rn(b));
    return __halves2half2(__float2half_rn(ra), __float2half_rn(rb));
}

__global__ void prep_kernel(const float* __restrict__ x, float* __restrict__ out) {
    __shared__ float scr[NG][4];
    __shared__ float out8[NG];
    __shared__ float cnorm2;
    __shared__ float xs[NG][ND];
    __shared__ float cs[ND];

    const int s    = blockIdx.x;
    const int j    = threadIdx.x;       // 0..127
    const int lane = j & 31;
    const int warp = j >> 5;

    float xg[NG];
    #pragma unroll
    for (int g = 0; g < NG; g++) xg[g] = x[(s * NG + g) * ND + j];

    float v[NG];
    #pragma unroll
    for (int g = 0; g < NG; g++) v[g] = xg[g] * xg[g];
    reduce8(v, scr, out8, lane, warp, j);
    float xn[NG];
    float sum = 0.f;
    #pragma unroll
    for (int g = 0; g < NG; g++) {
        float nrm = fmaxf(sqrtf(out8[g]), 1e-12f);
        xn[g] = xg[g] / nrm;
        sum += xn[g];
    }

    float cent = sum * 0.125f;
    {
        float c2 = cent * cent;
        #pragma unroll
        for (int off = 16; off > 0; off >>= 1)
            c2 += __shfl_xor_sync(0xffffffffu, c2, off);
        if (lane == 0) scr[0][warp] = c2;
        __syncthreads();
        if (j == 0) cnorm2 = scr[0][0] + scr[0][1] + scr[0][2] + scr[0][3];
        __syncthreads();
    }
    float centv = 30.f * cent / fmaxf(sqrtf(cnorm2), 1e-8f);

    float exc[NG];
    #pragma unroll
    for (int g = 0; g < NG; g++) {
        exc[g] = (sum - xn[g]) * (1.0f / 7.0f);
        v[g] = exc[g] * exc[g];
    }
    reduce8(v, scr, out8, lane, warp, j);
    float e2[NG];
    #pragma unroll
    for (int g = 0; g < NG; g++) e2[g] = out8[g];
    #pragma unroll
    for (int g = 0; g < NG; g++)
        v[g] = xn[g] * exc[g] / fmaxf(sqrtf(e2[g]), 1e-8f);
    reduce8(v, scr, out8, lane, warp, j);
    if (j < NG) g_lbl[s * NG + j] = fmaxf(30.f * out8[j], 1e-6f);

    #pragma unroll
    for (int g = 0; g < NG; g++) xs[g][j] = xn[g];
    cs[j] = centv;
    __syncthreads();

    // A': [Ah(128) | Al(128)] fp16 pairs
    const int abase = s * NG * (KC/2);
    #pragma unroll
    for (int it = 0; it < (NG * (KC/2)) / 128; it++) {   // 8 iters
        int idx = it * 128 + j;
        int r  = idx / (KC/2);
        int p  = idx % (KC/2);
        int pm = p & 63, blk = p >> 6;
        float v0 = xs[r][2*pm], v1 = xs[r][2*pm+1];
        g_A2[abase + idx] = (blk == 0) ? hi_pair(v0, v1) : lo_pair(v0, v1);
    }

    // B': [Bh | Bh]
    #pragma unroll
    for (int p = j; p < (KC/2); p += 128) {
        int pm = p & 63;
        g_B2[s * (KC/2) + p] = hi_pair(cs[2*pm], cs[2*pm+1]);
    }

    if (s == 0 && j == 0) out[0] = 0.f;   // zero accumulator (d_out is poisoned)
}

// ---------------------------------------------------------------------------
// Kernel 2: HMMA GEMM (fp16 2-term) + fused online log-softmax.
// A fragments register-resident (loaded once); only B streamed via LDSM.
// 128 CTAs x 256 threads; warp grid 4m x 2n, warp tile 32x32.
// ---------------------------------------------------------------------------
#define SM_A     0
#define SM_B0    (BM * ROWB)               // 65536
#define SM_B1    (SM_B0 + BN * ROWB)       // 98304
#define SM_TOTAL (SM_B1 + BN * ROWB)       // 131072

__global__ void __launch_bounds__(NT, 1) gemm_kernel(float* __restrict__ out) {
    extern __shared__ char smem[];
    __shared__ float zbuf[BM][2];
    __shared__ float cbuf[BM][2];
    __shared__ float red[8];

    const uint32_t sb = smem_u32(smem);
    const int tid  = threadIdx.x;
    const int lane = tid & 31;
    const int wid  = tid >> 5;
    const int wm   = wid & 3;        // 0..3  (32-row slices)
    const int wn   = wid >> 2;       // 0..1  (32-col slices)
    const int br0  = blockIdx.x * BM;
    const int td   = blockIdx.x >> 2;   // B tile holding this block's diagonal

    const char* gA = (const char*)g_A2;
    const char* gB = (const char*)g_B2;

    // ---- prologue: A tile + B tile 0 (one cp.async group) ----
    #pragma unroll
    for (int ii = 0; ii < (BM * NCH) / NT; ii++) {     // 16 iters
        int idx = ii * NT + tid;
        int c = idx % NCH, r = idx / NCH;
        CP16(sb + SM_A + r * ROWB + ((c ^ (r & 7)) << 4),
             gA + (size_t)(br0 + r) * ROWB + c * 16);
    }
    #pragma unroll
    for (int ii = 0; ii < (BN * NCH) / NT; ii++) {     // 8 iters
        int idx = ii * NT + tid;
        int c = idx % NCH, n = idx / NCH;
        CP16(sb + SM_B0 + n * ROWB + ((c ^ (n & 7)) << 4),
             gB + (size_t)n * ROWB + c * 16);
    }
    CP_COMMIT();

    // ---- B fragment addressing ----
    uint32_t bOff[2], bS[2];
    #pragma unroll
    for (int j2 = 0; j2 < 2; j2++) {
        int n = wn * 32 + j2 * 16 + ((lane >> 4) & 1) * 8 + (lane & 7);
        bOff[j2] = n * ROWB;
        bS[j2] = n & 7;
    }
    const uint32_t cbB = (lane >> 3) & 1;

    // row slots: slot = mi*2 + h, row = wm*32 + mi*16 + h*8 + lane/4
    int rl[4], dc[4];
    float zsum[4], zcorr[4];
    #pragma unroll
    for (int sl = 0; sl < 4; sl++) {
        int mi = sl >> 1, h = sl & 1;
        rl[sl] = wm * 32 + mi * 16 + h * 8 + (lane >> 2);
        dc[sl] = (br0 + rl[sl]) >> 3;
        zsum[sl] = 0.f; zcorr[sl] = 0.f;
    }

    // ---- wait for A + B0, then load ALL A fragments into registers ----
    CP_WAIT0();
    __syncthreads();

    unsigned afr[2][NKS][4];    // 128 registers: A resident for the whole kernel
    {
        const uint32_t cbA = (lane >> 4);
        #pragma unroll
        for (int mi = 0; mi < 2; mi++) {
            int row = wm * 32 + mi * 16 + (lane & 15);
            uint32_t base = sb + SM_A + row * ROWB;
            uint32_t s8 = row & 7;
            #pragma unroll
            for (int ks = 0; ks < NKS; ks++)
                ldsm4(afr[mi][ks], base + ((((2u*ks) | cbA) ^ s8) << 4));
        }
    }

    const uint32_t bufB[2] = { sb + SM_B0, sb + SM_B1 };

    for (int t = 0; t < NTILES; t++) {
        // B(t) is complete (waited last iteration); all warps past barrier ->
        // safe to prefetch B(t+1) into the buffer read at t-1.
        if (t + 1 < NTILES) {
            const uint32_t bb = bufB[(t + 1) & 1];
            #pragma unroll
            for (int ii = 0; ii < (BN * NCH) / NT; ii++) {
                int idx = ii * NT + tid;
                int c = idx % NCH, n = idx / NCH;
                CP16(bb + n * ROWB + ((c ^ (n & 7)) << 4),
                     gB + (size_t)((t + 1) * BN + n) * ROWB + c * 16);
            }
            CP_COMMIT();
        }

        const uint32_t bcur = bufB[t & 1];
        float acc[2][4][4];
        #pragma unroll
        for (int mi = 0; mi < 2; mi++)
            #pragma unroll
            for (int nj = 0; nj < 4; nj++)
                #pragma unroll
                for (int q = 0; q < 4; q++) acc[mi][nj][q] = 0.f;

        #pragma unroll
        for (int ks = 0; ks < NKS; ks++) {          // 16 steps: 2 LDSM + 8 mma
            const uint32_t c2 = 2u * ks;
            unsigned bf[2][4];
            #pragma unroll
            for (int j2 = 0; j2 < 2; j2++)
                ldsm4(bf[j2], bcur + bOff[j2] + (((c2 | cbB) ^ bS[j2]) << 4));
            #pragma unroll
            for (int mi = 0; mi < 2; mi++)
                #pragma unroll
                for (int nj = 0; nj < 4; nj++)
                    mma16816(acc[mi][nj], afr[mi][ks],
                             bf[nj >> 1][(nj & 1) * 2], bf[nj >> 1][(nj & 1) * 2 + 1]);
        }

        // fused epilogue: clamp + exp + online Z (logits <= 30, no max pass)
        if (t == td) {
            #pragma unroll
            for (int mi = 0; mi < 2; mi++)
                #pragma unroll
                for (int nj = 0; nj < 4; nj++) {
                    int cb = t * BN + wn * 32 + nj * 8 + (lane & 3) * 2;
                    float e0 = __expf(fmaxf(acc[mi][nj][0], 1e-6f) - 30.f);
                    float e1 = __expf(fmaxf(acc[mi][nj][1], 1e-6f) - 30.f);
                    float e2 = __expf(fmaxf(acc[mi][nj][2], 1e-6f) - 30.f);
                    float e3 = __expf(fmaxf(acc[mi][nj][3], 1e-6f) - 30.f);
                    zsum[mi*2]   += e0 + e1;
                    zsum[mi*2+1] += e2 + e3;
                    if (cb     == dc[mi*2])   zcorr[mi*2]   += e0;
                    if (cb + 1 == dc[mi*2])   zcorr[mi*2]   += e1;
                    if (cb     == dc[mi*2+1]) zcorr[mi*2+1] += e2;
                    if (cb + 1 == dc[mi*2+1]) zcorr[mi*2+1] += e3;
                }
        } else {
            #pragma unroll
            for (int mi = 0; mi < 2; mi++)
                #pragma unroll
                for (int nj = 0; nj < 4; nj++) {
                    float e0 = __expf(fmaxf(acc[mi][nj][0], 1e-6f) - 30.f);
                    float e1 = __expf(fmaxf(acc[mi][nj][1], 1e-6f) - 30.f);
                    float e2 = __expf(fmaxf(acc[mi][nj][2], 1e-6f) - 30.f);
                    float e3 = __expf(fmaxf(acc[mi][nj][3], 1e-6f) - 30.f);
                    zsum[mi*2]   += e0 + e1;
                    zsum[mi*2+1] += e2 + e3;
                }
        }

        // wait for B(t+1) and re-align warps before next iteration's prefetch
        if (t + 1 < NTILES) {
            CP_WAIT0();
            __syncthreads();
        }
    }

    // reduce z across the 4 lanes of each quad (same row)
    #pragma unroll
    for (int sl = 0; sl < 4; sl++) {
        float z = zsum[sl], c = zcorr[sl];
        z += __shfl_xor_sync(0xffffffffu, z, 1);
        z += __shfl_xor_sync(0xffffffffu, z, 2);
        c += __shfl_xor_sync(0xffffffffu, c, 1);
        c += __shfl_xor_sync(0xffffffffu, c, 2);
        if ((lane & 3) == 0) { zbuf[rl[sl]][wn] = z; cbuf[rl[sl]][wn] = c; }
    }
    __syncthreads();

    // per-row loss + block reduce + single atomicAdd
    float loss = 0.f;
    if (tid < BM) {
        int row = br0 + tid;
        float lbl = g_lbl[row];
        float Z = zbuf[tid][0] + zbuf[tid][1] - cbuf[tid][0] - cbuf[tid][1]
                  + __expf(lbl - 30.f);
        loss = 30.f + logf(Z) - lbl;
    }
    #pragma unroll
    for (int off = 16; off > 0; off >>= 1)
        loss += __shfl_xor_sync(0xffffffffu, loss, off);
    if (lane == 0) red[wid] = loss;
    __syncthreads();
    if (tid == 0) {
        float tot = 0.f;
        #pragma unroll
        for (int q = 0; q < 8; q++) tot += red[q];
        atomicAdd(out, tot * (1.f / (float)NR));
    }
}

// ---------------------------------------------------------------------------
extern "C" void kernel_launch(void* const* d_in, const int* in_sizes, int n_in,
                              void* d_out, int out_size) {
    const float* x = (const float*)d_in[0];
    float* out = (float*)d_out;

    prep_kernel<<<NS, 128>>>(x, out);

    cudaFuncSetAttribute(gemm_kernel, cudaFuncAttributeMaxDynamicSharedMemorySize, SM_TOTAL);
    gemm_kernel<<<NR / BM, NT, SM_TOTAL>>>(out);
}

// round 10
// speedup vs baseline: 1.9865x; 1.4464x over previous
#include <cuda_runtime.h>
#include <cuda_fp16.h>
#include <cstdint>
#include <math.h>

#define NS 2048      // speakers
#define NG 8         // utts per speaker
#define ND 128       // embed dim
#define NR (NS*NG)   // 16384 rows
#define KC 128       // plain fp16, K = embed dim
#define NCH (KC/8)   // 16 16-byte chunks per row
#define ROWB (KC*2)  // 256 bytes per row
#define BM 128
#define BN 64
#define NTILES (NS/BN)   // 32
#define NT 256           // threads per CTA
#define NKS (KC/16)      // 8 k-steps

#define LOG2E 1.4426950408889634f
#define CEXP  (30.0f * LOG2E)      // 43.2808...

// ---------------------------------------------------------------------------
// device globals (no allocation allowed)
// ---------------------------------------------------------------------------
__device__ float g_lbl[NR];                            // true label logit
__device__ __align__(16) __half2 g_A2[NR * (KC/2)];    // [row][64] pairs (xn fp16)
__device__ __align__(16) __half2 g_B2[NS * (KC/2)];    // [spk][64] pairs (30*log2e*cent_n)

// ---------------------------------------------------------------------------
// PTX helpers (plain sm_80/90 — safe for compute_103)
// ---------------------------------------------------------------------------
__device__ __forceinline__ uint32_t smem_u32(const void* p) {
    uint32_t a;
    asm("{ .reg .u64 t; cvta.to.shared.u64 t, %1; cvt.u32.u64 %0, t; }" : "=r"(a) : "l"(p));
    return a;
}
#define CP16(dst32, gptr) \
    asm volatile("cp.async.cg.shared.global [%0], [%1], 16;" \
        :: "r"(dst32), "l"(__cvta_generic_to_global(gptr)) : "memory")
#define CP_COMMIT() asm volatile("cp.async.commit_group;" ::: "memory")
#define CP_WAIT0()  asm volatile("cp.async.wait_group 0;" ::: "memory")

__device__ __forceinline__ void ldsm4(unsigned r[4], uint32_t addr) {
    asm volatile("ldmatrix.sync.aligned.m8n8.x4.shared.b16 {%0,%1,%2,%3}, [%4];"
        : "=r"(r[0]), "=r"(r[1]), "=r"(r[2]), "=r"(r[3]) : "r"(addr));
}
__device__ __forceinline__ void mma16816(float d[4], const unsigned a[4],
                                         unsigned b0, unsigned b1) {
    asm volatile("mma.sync.aligned.m16n8k16.row.col.f32.f16.f16.f32 "
        "{%0,%1,%2,%3}, {%4,%5,%6,%7}, {%8,%9}, {%0,%1,%2,%3};"
        : "+f"(d[0]), "+f"(d[1]), "+f"(d[2]), "+f"(d[3])
        : "r"(a[0]), "r"(a[1]), "r"(a[2]), "r"(a[3]), "r"(b0), "r"(b1));
}

// ---------------------------------------------------------------------------
// Kernel 1: per-speaker prep
// ---------------------------------------------------------------------------
__device__ __forceinline__ void reduce8(const float v[NG], float (*scr)[4],
                                        float* out8, int lane, int warp, int tid) {
    #pragma unroll
    for (int g = 0; g < NG; g++) {
        float r = v[g];
        #pragma unroll
        for (int off = 16; off > 0; off >>= 1)
            r += __shfl_xor_sync(0xffffffffu, r, off);
        if (lane == 0) scr[g][warp] = r;
    }
    __syncthreads();
    if (tid < NG) out8[tid] = scr[tid][0] + scr[tid][1] + scr[tid][2] + scr[tid][3];
    __syncthreads();
}

__device__ __forceinline__ __half2 hi_pair(float a, float b) {
    return __halves2half2(__float2half_rn(a), __float2half_rn(b));
}

__global__ void prep_kernel(const float* __restrict__ x, float* __restrict__ out) {
    __shared__ float scr[NG][4];
    __shared__ float out8[NG];
    __shared__ float cnorm2;
    __shared__ float xs[NG][ND];
    __shared__ float cs[ND];

    const int s    = blockIdx.x;
    const int j    = threadIdx.x;       // 0..127
    const int lane = j & 31;
    const int warp = j >> 5;

    float xg[NG];
    #pragma unroll
    for (int g = 0; g < NG; g++) xg[g] = x[(s * NG + g) * ND + j];

    float v[NG];
    #pragma unroll
    for (int g = 0; g < NG; g++) v[g] = xg[g] * xg[g];
    reduce8(v, scr, out8, lane, warp, j);
    float xn[NG];
    float sum = 0.f;
    #pragma unroll
    for (int g = 0; g < NG; g++) {
        float nrm = fmaxf(sqrtf(out8[g]), 1e-12f);
        xn[g] = xg[g] / nrm;
        sum += xn[g];
    }

    float cent = sum * 0.125f;
    {
        float c2 = cent * cent;
        #pragma unroll
        for (int off = 16; off > 0; off >>= 1)
            c2 += __shfl_xor_sync(0xffffffffu, c2, off);
        if (lane == 0) scr[0][warp] = c2;
        __syncthreads();
        if (j == 0) cnorm2 = scr[0][0] + scr[0][1] + scr[0][2] + scr[0][3];
        __syncthreads();
    }
    // pre-scale centroid by 30*log2e: acc is then logit*log2e directly
    float centv = (30.f * LOG2E) * cent / fmaxf(sqrtf(cnorm2), 1e-8f);

    float exc[NG];
    #pragma unroll
    for (int g = 0; g < NG; g++) {
        exc[g] = (sum - xn[g]) * (1.0f / 7.0f);
        v[g] = exc[g] * exc[g];
    }
    reduce8(v, scr, out8, lane, warp, j);
    float e2[NG];
    #pragma unroll
    for (int g = 0; g < NG; g++) e2[g] = out8[g];
    #pragma unroll
    for (int g = 0; g < NG; g++)
        v[g] = xn[g] * exc[g] / fmaxf(sqrtf(e2[g]), 1e-8f);
    reduce8(v, scr, out8, lane, warp, j);
    if (j < NG) g_lbl[s * NG + j] = fmaxf(30.f * out8[j], 1e-6f);

    #pragma unroll
    for (int g = 0; g < NG; g++) xs[g][j] = xn[g];
    cs[j] = centv;
    __syncthreads();

    // A': plain fp16 pairs (64 per row)
    const int abase = s * NG * (KC/2);
    #pragma unroll
    for (int it = 0; it < (NG * (KC/2)) / 128; it++) {   // 4 iters
        int idx = it * 128 + j;
        int r = idx >> 6;
        int p = idx & 63;
        g_A2[abase + idx] = hi_pair(xs[r][2*p], xs[r][2*p+1]);
    }

    // B': fp16 pairs of pre-scaled centroid
    if (j < (KC/2)) g_B2[s * (KC/2) + j] = hi_pair(cs[2*j], cs[2*j+1]);

    if (s == 0 && j == 0) out[0] = 0.f;   // zero accumulator (d_out is poisoned)
}

// ---------------------------------------------------------------------------
// Kernel 2: HMMA GEMM (plain fp16, K=128) + fused online log-softmax.
// A fragments register-resident (64 regs); B streamed, double-buffered.
// Epilogue of tile t-1 interleaved into the mma loop of tile t.
// 128 CTAs x 256 threads; warp grid 4m x 2n, warp tile 32x32.
// acc values are logit*log2e; e = exp2f(acc - 30*log2e).
// ---------------------------------------------------------------------------
#define SM_A     0
#define SM_B0    (BM * ROWB)               // 32768
#define SM_B1    (SM_B0 + BN * ROWB)       // 49152
#define SM_TOTAL (SM_B1 + BN * ROWB)       // 65536

__global__ void __launch_bounds__(NT, 1) gemm_kernel(float* __restrict__ out) {
    extern __shared__ char smem[];
    __shared__ float zbuf[BM][2];
    __shared__ float cbuf[BM][2];
    __shared__ float red[8];

    const uint32_t sb = smem_u32(smem);
    const int tid  = threadIdx.x;
    const int lane = tid & 31;
    const int wid  = tid >> 5;
    const int wm   = wid & 3;        // 0..3  (32-row slices)
    const int wn   = wid >> 2;       // 0..1  (32-col slices)
    const int br0  = blockIdx.x * BM;
    const int td   = blockIdx.x >> 2;   // B tile holding this block's diagonal

    const char* gA = (const char*)g_A2;
    const char* gB = (const char*)g_B2;

    // ---- prologue: A tile + B tile 0 ----
    #pragma unroll
    for (int ii = 0; ii < (BM * NCH) / NT; ii++) {     // 8 iters
        int idx = ii * NT + tid;
        int c = idx % NCH, r = idx / NCH;
        CP16(sb + SM_A + r * ROWB + ((c ^ (r & 7)) << 4),
             gA + (size_t)(br0 + r) * ROWB + c * 16);
    }
    #pragma unroll
    for (int ii = 0; ii < (BN * NCH) / NT; ii++) {     // 4 iters
        int idx = ii * NT + tid;
        int c = idx % NCH, n = idx / NCH;
        CP16(sb + SM_B0 + n * ROWB + ((c ^ (n & 7)) << 4),
             gB + (size_t)n * ROWB + c * 16);
    }
    CP_COMMIT();

    // ---- B fragment addressing ----
    uint32_t bOff[2], bS[2];
    #pragma unroll
    for (int j2 = 0; j2 < 2; j2++) {
        int n = wn * 32 + j2 * 16 + ((lane >> 4) & 1) * 8 + (lane & 7);
        bOff[j2] = n * ROWB;
        bS[j2] = n & 7;
    }
    const uint32_t cbB = (lane >> 3) & 1;

    // row slots: slot = mi*2 + h, row = wm*32 + mi*16 + h*8 + lane/4
    int rl[4], dc[4];
    float zsum[4], zcorr[4];
    #pragma unroll
    for (int sl = 0; sl < 4; sl++) {
        int mi = sl >> 1, h = sl & 1;
        rl[sl] = wm * 32 + mi * 16 + h * 8 + (lane >> 2);
        dc[sl] = (br0 + rl[sl]) >> 3;
        zsum[sl] = 0.f; zcorr[sl] = 0.f;
    }

    // ---- wait for A + B0, then load ALL A fragments into registers ----
    CP_WAIT0();
    __syncthreads();

    unsigned afr[2][NKS][4];    // 64 registers
    {
        const uint32_t cbA = (lane >> 4);
        #pragma unroll
        for (int mi = 0; mi < 2; mi++) {
            int row = wm * 32 + mi * 16 + (lane & 15);
            uint32_t base = sb + SM_A + row * ROWB;
            uint32_t s8 = row & 7;
            #pragma unroll
            for (int ks = 0; ks < NKS; ks++)
                ldsm4(afr[mi][ks], base + ((((2u*ks) | cbA) ^ s8) << 4));
        }
    }

    const uint32_t bufB[2] = { sb + SM_B0, sb + SM_B1 };
    const float CLAMP2 = 1e-6f * LOG2E;
    const int colBase = wn * 32 + (lane & 3) * 2;

    float acc[2][4][4], accPrev[2][4][4];

    for (int t = 0; t < NTILES; t++) {
        // B(t) ready and all warps past barrier -> prefetch B(t+1)
        if (t + 1 < NTILES) {
            const uint32_t bb = bufB[(t + 1) & 1];
            #pragma unroll
            for (int ii = 0; ii < (BN * NCH) / NT; ii++) {
                int idx = ii * NT + tid;
                int c = idx % NCH, n = idx / NCH;
                CP16(bb + n * ROWB + ((c ^ (n & 7)) << 4),
                     gB + (size_t)((t + 1) * BN + n) * ROWB + c * 16);
            }
            CP_COMMIT();
        }

        const uint32_t bcur = bufB[t & 1];
        #pragma unroll
        for (int mi = 0; mi < 2; mi++)
            #pragma unroll
            for (int nj = 0; nj < 4; nj++)
                #pragma unroll
                for (int q = 0; q < 4; q++) acc[mi][nj][q] = 0.f;

        const bool havePrev = (t > 0);
        const int  tt = t - 1;
        const bool isDiag = (tt == td);

        #pragma unroll
        for (int ks = 0; ks < NKS; ks++) {          // 8 steps: 2 LDSM + 8 mma
            const uint32_t c2 = 2u * ks;
            unsigned bf[2][4];
            #pragma unroll
            for (int j2 = 0; j2 < 2; j2++)
                ldsm4(bf[j2], bcur + bOff[j2] + (((c2 | cbB) ^ bS[j2]) << 4));
            #pragma unroll
            for (int mi = 0; mi < 2; mi++)
                #pragma unroll
                for (int nj = 0; nj < 4; nj++)
                    mma16816(acc[mi][nj], afr[mi][ks],
                             bf[nj >> 1][(nj & 1) * 2], bf[nj >> 1][(nj & 1) * 2 + 1]);

            // deferred epilogue of tile t-1: one (mi,nj) group per k-step
            if (havePrev) {
                const int mi = ks >> 2, nj = ks & 3;
                const float* a = accPrev[mi][nj];
                float e0 = exp2f(fmaxf(a[0], CLAMP2) - CEXP);
                float e1 = exp2f(fmaxf(a[1], CLAMP2) - CEXP);
                float e2 = exp2f(fmaxf(a[2], CLAMP2) - CEXP);
                float e3 = exp2f(fmaxf(a[3], CLAMP2) - CEXP);
                zsum[mi*2]   += e0 + e1;
                zsum[mi*2+1] += e2 + e3;
                if (isDiag) {
                    int cb = tt * BN + nj * 8 + colBase;
                    if (cb     == dc[mi*2])   zcorr[mi*2]   += e0;
                    if (cb + 1 == dc[mi*2])   zcorr[mi*2]   += e1;
                    if (cb     == dc[mi*2+1]) zcorr[mi*2+1] += e2;
                    if (cb + 1 == dc[mi*2+1]) zcorr[mi*2+1] += e3;
                }
            }
        }

        // stash for deferred epilogue
        #pragma unroll
        for (int mi = 0; mi < 2; mi++)
            #pragma unroll
            for (int nj = 0; nj < 4; nj++)
                #pragma unroll
                for (int q = 0; q < 4; q++) accPrev[mi][nj][q] = acc[mi][nj][q];

        if (t + 1 < NTILES) {
            CP_WAIT0();
            __syncthreads();
        }
    }

    // tail epilogue: tile NTILES-1
    {
        const int tt = NTILES - 1;
        const bool isDiag = (tt == td);
        #pragma unroll
        for (int g = 0; g < 8; g++) {
            const int mi = g >> 2, nj = g & 3;
            const float* a = accPrev[mi][nj];
            float e0 = exp2f(fmaxf(a[0], CLAMP2) - CEXP);
            float e1 = exp2f(fmaxf(a[1], CLAMP2) - CEXP);
            float e2 = exp2f(fmaxf(a[2], CLAMP2) - CEXP);
            float e3 = exp2f(fmaxf(a[3], CLAMP2) - CEXP);
            zsum[mi*2]   += e0 + e1;
            zsum[mi*2+1] += e2 + e3;
            if (isDiag) {
                int cb = tt * BN + nj * 8 + colBase;
                if (cb     == dc[mi*2])   zcorr[mi*2]   += e0;
                if (cb + 1 == dc[mi*2])   zcorr[mi*2]   += e1;
                if (cb     == dc[mi*2+1]) zcorr[mi*2+1] += e2;
                if (cb + 1 == dc[mi*2+1]) zcorr[mi*2+1] += e3;
            }
        }
    }

    // reduce z across the 4 lanes of each quad (same row)
    #pragma unroll
    for (int sl = 0; sl < 4; sl++) {
        float z = zsum[sl], c = zcorr[sl];
        z += __shfl_xor_sync(0xffffffffu, z, 1);
        z += __shfl_xor_sync(0xffffffffu, z, 2);
        c += __shfl_xor_sync(0xffffffffu, c, 1);
        c += __shfl_xor_sync(0xffffffffu, c, 2);
        if ((lane & 3) == 0) { zbuf[rl[sl]][wn] = z; cbuf[rl[sl]][wn] = c; }
    }
    __syncthreads();

    // per-row loss + block reduce + single atomicAdd
    float loss = 0.f;
    if (tid < BM) {
        int row = br0 + tid;
        float lbl = g_lbl[row];
        float Z = zbuf[tid][0] + zbuf[tid][1] - cbuf[tid][0] - cbuf[tid][1]
                  + exp2f(lbl * LOG2E - CEXP);
        loss = 30.f + logf(Z) - lbl;
    }
    #pragma unroll
    for (int off = 16; off > 0; off >>= 1)
        loss += __shfl_xor_sync(0xffffffffu, loss, off);
    if (lane == 0) red[wid] = loss;
    __syncthreads();
    if (tid == 0) {
        float tot = 0.f;
        #pragma unroll
        for (int q = 0; q < 8; q++) tot += red[q];
        atomicAdd(out, tot * (1.f / (float)NR));
    }
}

// ---------------------------------------------------------------------------
extern "C" void kernel_launch(void* const* d_in, const int* in_sizes, int n_in,
                              void* d_out, int out_size) {
    const float* x = (const float*)d_in[0];
    float* out = (float*)d_out;

    prep_kernel<<<NS, 128>>>(x, out);

    cudaFuncSetAttribute(gemm_kernel, cudaFuncAttributeMaxDynamicSharedMemorySize, SM_TOTAL);
    gemm_kernel<<<NR / BM, NT, SM_TOTAL>>>(out);
}

// round 11
// speedup vs baseline: 2.0827x; 1.0484x over previous
#include <cuda_runtime.h>
#include <cuda_fp16.h>
#include <cstdint>
#include <math.h>

#define NS 2048      // speakers
#define NG 8         // utts per speaker
#define ND 128       // embed dim
#define NR (NS*NG)   // 16384 rows
#define KC 128       // plain fp16, K = embed dim
#define NCH (KC/8)   // 16 16-byte chunks per row
#define ROWB (KC*2)  // 256 bytes per row
#define BM 128
#define BN 64
#define NTILES (NS/BN)   // 32
#define NT 512           // threads per CTA (16 warps = 4/SMSP)
#define NKS (KC/16)      // 8 k-steps

#define LOG2E 1.4426950408889634f
#define CEXP  (30.0f * LOG2E)

// ---------------------------------------------------------------------------
// device globals (no allocation allowed)
// ---------------------------------------------------------------------------
__device__ float g_lbl[NR];                            // true label logit
__device__ __align__(16) __half2 g_A2[NR * (KC/2)];    // [row][64] pairs (xn fp16)
__device__ __align__(16) __half2 g_B2[NS * (KC/2)];    // [spk][64] pairs (30*log2e*cent_n)

// ---------------------------------------------------------------------------
// PTX helpers (plain sm_80/90 — safe for compute_103)
// ---------------------------------------------------------------------------
__device__ __forceinline__ uint32_t smem_u32(const void* p) {
    uint32_t a;
    asm("{ .reg .u64 t; cvta.to.shared.u64 t, %1; cvt.u32.u64 %0, t; }" : "=r"(a) : "l"(p));
    return a;
}
#define CP16(dst32, gptr) \
    asm volatile("cp.async.cg.shared.global [%0], [%1], 16;" \
        :: "r"(dst32), "l"(__cvta_generic_to_global(gptr)) : "memory")
#define CP_COMMIT() asm volatile("cp.async.commit_group;" ::: "memory")
#define CP_WAIT0()  asm volatile("cp.async.wait_group 0;" ::: "memory")

__device__ __forceinline__ void ldsm4(unsigned r[4], uint32_t addr) {
    asm volatile("ldmatrix.sync.aligned.m8n8.x4.shared.b16 {%0,%1,%2,%3}, [%4];"
        : "=r"(r[0]), "=r"(r[1]), "=r"(r[2]), "=r"(r[3]) : "r"(addr));
}
__device__ __forceinline__ void mma16816(float d[4], const unsigned a[4],
                                         unsigned b0, unsigned b1) {
    asm volatile("mma.sync.aligned.m16n8k16.row.col.f32.f16.f16.f32 "
        "{%0,%1,%2,%3}, {%4,%5,%6,%7}, {%8,%9}, {%0,%1,%2,%3};"
        : "+f"(d[0]), "+f"(d[1]), "+f"(d[2]), "+f"(d[3])
        : "r"(a[0]), "r"(a[1]), "r"(a[2]), "r"(a[3]), "r"(b0), "r"(b1));
}

// ---------------------------------------------------------------------------
// Kernel 1: per-speaker prep
// ---------------------------------------------------------------------------
__device__ __forceinline__ void reduce8(const float v[NG], float (*scr)[4],
                                        float* out8, int lane, int warp, int tid) {
    #pragma unroll
    for (int g = 0; g < NG; g++) {
        float r = v[g];
        #pragma unroll
        for (int off = 16; off > 0; off >>= 1)
            r += __shfl_xor_sync(0xffffffffu, r, off);
        if (lane == 0) scr[g][warp] = r;
    }
    __syncthreads();
    if (tid < NG) out8[tid] = scr[tid][0] + scr[tid][1] + scr[tid][2] + scr[tid][3];
    __syncthreads();
}

__device__ __forceinline__ __half2 hi_pair(float a, float b) {
    return __halves2half2(__float2half_rn(a), __float2half_rn(b));
}

__global__ void prep_kernel(const float* __restrict__ x, float* __restrict__ out) {
    __shared__ float scr[NG][4];
    __shared__ float out8[NG];
    __shared__ float cnorm2;
    __shared__ float xs[NG][ND];
    __shared__ float cs[ND];

    const int s    = blockIdx.x;
    const int j    = threadIdx.x;       // 0..127
    const int lane = j & 31;
    const int warp = j >> 5;

    float xg[NG];
    #pragma unroll
    for (int g = 0; g < NG; g++) xg[g] = x[(s * NG + g) * ND + j];

    float v[NG];
    #pragma unroll
    for (int g = 0; g < NG; g++) v[g] = xg[g] * xg[g];
    reduce8(v, scr, out8, lane, warp, j);
    float xn[NG];
    float sum = 0.f;
    #pragma unroll
    for (int g = 0; g < NG; g++) {
        float nrm = fmaxf(sqrtf(out8[g]), 1e-12f);
        xn[g] = xg[g] / nrm;
        sum += xn[g];
    }

    float cent = sum * 0.125f;
    {
        float c2 = cent * cent;
        #pragma unroll
        for (int off = 16; off > 0; off >>= 1)
            c2 += __shfl_xor_sync(0xffffffffu, c2, off);
        if (lane == 0) scr[0][warp] = c2;
        __syncthreads();
        if (j == 0) cnorm2 = scr[0][0] + scr[0][1] + scr[0][2] + scr[0][3];
        __syncthreads();
    }
    // pre-scale centroid by 30*log2e: acc is then logit*log2e directly
    float centv = (30.f * LOG2E) * cent / fmaxf(sqrtf(cnorm2), 1e-8f);

    float exc[NG];
    #pragma unroll
    for (int g = 0; g < NG; g++) {
        exc[g] = (sum - xn[g]) * (1.0f / 7.0f);
        v[g] = exc[g] * exc[g];
    }
    reduce8(v, scr, out8, lane, warp, j);
    float e2[NG];
    #pragma unroll
    for (int g = 0; g < NG; g++) e2[g] = out8[g];
    #pragma unroll
    for (int g = 0; g < NG; g++)
        v[g] = xn[g] * exc[g] / fmaxf(sqrtf(e2[g]), 1e-8f);
    reduce8(v, scr, out8, lane, warp, j);
    if (j < NG) g_lbl[s * NG + j] = fmaxf(30.f * out8[j], 1e-6f);

    #pragma unroll
    for (int g = 0; g < NG; g++) xs[g][j] = xn[g];
    cs[j] = centv;
    __syncthreads();

    // A': plain fp16 pairs (64 per row)
    const int abase = s * NG * (KC/2);
    #pragma unroll
    for (int it = 0; it < (NG * (KC/2)) / 128; it++) {   // 4 iters
        int idx = it * 128 + j;
        int r = idx >> 6;
        int p = idx & 63;
        g_A2[abase + idx] = hi_pair(xs[r][2*p], xs[r][2*p+1]);
    }

    // B': fp16 pairs of pre-scaled centroid
    if (j < (KC/2)) g_B2[s * (KC/2) + j] = hi_pair(cs[2*j], cs[2*j+1]);

    if (s == 0 && j == 0) out[0] = 0.f;   // zero accumulator (d_out is poisoned)
}

// ---------------------------------------------------------------------------
// Kernel 2: HMMA GEMM (plain fp16, K=128) + fused online log-softmax.
// 128 CTAs x 512 threads (16 warps = 4/SMSP). Warp grid 4m x 4n,
// warp tile 32x16. A fragments register-resident; B double-buffered.
// acc values are logit*log2e; e = exp2f(acc - 30*log2e).
// ---------------------------------------------------------------------------
#define SM_A     0
#define SM_B0    (BM * ROWB)               // 32768
#define SM_B1    (SM_B0 + BN * ROWB)       // 49152
#define SM_TOTAL (SM_B1 + BN * ROWB)       // 65536

__global__ void __launch_bounds__(NT, 1) gemm_kernel(float* __restrict__ out) {
    extern __shared__ char smem[];
    __shared__ float zbuf[BM][4];
    __shared__ float cbuf[BM][4];
    __shared__ float red[16];

    const uint32_t sb = smem_u32(smem);
    const int tid  = threadIdx.x;
    const int lane = tid & 31;
    const int wid  = tid >> 5;
    const int wm   = wid & 3;        // 0..3  (32-row slices)
    const int wn   = wid >> 2;       // 0..3  (16-col slices)
    const int br0  = blockIdx.x * BM;
    const int td   = blockIdx.x >> 2;   // B tile holding this block's diagonal

    const char* gA = (const char*)g_A2;
    const char* gB = (const char*)g_B2;

    // ---- prologue: A tile + B tile 0 ----
    #pragma unroll
    for (int ii = 0; ii < (BM * NCH) / NT; ii++) {     // 4 iters
        int idx = ii * NT + tid;
        int c = idx % NCH, r = idx / NCH;
        CP16(sb + SM_A + r * ROWB + ((c ^ (r & 7)) << 4),
             gA + (size_t)(br0 + r) * ROWB + c * 16);
    }
    #pragma unroll
    for (int ii = 0; ii < (BN * NCH) / NT; ii++) {     // 2 iters
        int idx = ii * NT + tid;
        int c = idx % NCH, n = idx / NCH;
        CP16(sb + SM_B0 + n * ROWB + ((c ^ (n & 7)) << 4),
             gB + (size_t)n * ROWB + c * 16);
    }
    CP_COMMIT();

    // ---- B fragment addressing: 16 cols per warp -> one ldsm4 per k-step ----
    uint32_t bOff, bS;
    {
        int n = wn * 16 + ((lane >> 4) & 1) * 8 + (lane & 7);
        bOff = n * ROWB;
        bS = n & 7;
    }
    const uint32_t cbB = (lane >> 3) & 1;

    // row slots: slot = mi*2 + h, row = wm*32 + mi*16 + h*8 + lane/4
    int rl[4], dc[4];
    float zsum[4], zcorr[4];
    #pragma unroll
    for (int sl = 0; sl < 4; sl++) {
        int mi = sl >> 1, h = sl & 1;
        rl[sl] = wm * 32 + mi * 16 + h * 8 + (lane >> 2);
        dc[sl] = (br0 + rl[sl]) >> 3;
        zsum[sl] = 0.f; zcorr[sl] = 0.f;
    }

    // ---- wait for A + B0, then load ALL A fragments into registers ----
    CP_WAIT0();
    __syncthreads();

    unsigned afr[2][NKS][4];    // 64 registers
    {
        const uint32_t cbA = (lane >> 4);
        #pragma unroll
        for (int mi = 0; mi < 2; mi++) {
            int row = wm * 32 + mi * 16 + (lane & 15);
            uint32_t base = sb + SM_A + row * ROWB;
            uint32_t s8 = row & 7;
            #pragma unroll
            for (int ks = 0; ks < NKS; ks++)
                ldsm4(afr[mi][ks], base + ((((2u*ks) | cbA) ^ s8) << 4));
        }
    }

    const uint32_t bufB[2] = { sb + SM_B0, sb + SM_B1 };
    const float CLAMP2 = 1e-6f * LOG2E;
    const int colBase = wn * 16 + (lane & 3) * 2;

    float acc[2][2][4], accPrev[2][2][4];

    for (int t = 0; t < NTILES; t++) {
        // B(t) ready and all warps past barrier -> prefetch B(t+1)
        if (t + 1 < NTILES) {
            const uint32_t bb = bufB[(t + 1) & 1];
            #pragma unroll
            for (int ii = 0; ii < (BN * NCH) / NT; ii++) {
                int idx = ii * NT + tid;
                int c = idx % NCH, n = idx / NCH;
                CP16(bb + n * ROWB + ((c ^ (n & 7)) << 4),
                     gB + (size_t)((t + 1) * BN + n) * ROWB + c * 16);
            }
            CP_COMMIT();
        }

        const uint32_t bcur = bufB[t & 1] + bOff;
        #pragma unroll
        for (int mi = 0; mi < 2; mi++)
            #pragma unroll
            for (int nj = 0; nj < 2; nj++)
                #pragma unroll
                for (int q = 0; q < 4; q++) acc[mi][nj][q] = 0.f;

        const bool havePrev = (t > 0);
        const int  tt = t - 1;
        const bool isDiag = (tt == td);

        #pragma unroll
        for (int ks = 0; ks < NKS; ks++) {          // 8 steps: 1 LDSM + 4 mma
            unsigned bf[4];
            ldsm4(bf, bcur + ((((2u*ks) | cbB) ^ bS) << 4));
            #pragma unroll
            for (int mi = 0; mi < 2; mi++)
                #pragma unroll
                for (int nj = 0; nj < 2; nj++)
                    mma16816(acc[mi][nj], afr[mi][ks], bf[nj * 2], bf[nj * 2 + 1]);

            // deferred epilogue of tile t-1: one (mi,nj) group per early k-step
            if (ks < 4 && havePrev) {
                const int mi = ks >> 1, nj = ks & 1;
                const float* a = accPrev[mi][nj];
                float e0 = exp2f(fmaxf(a[0], CLAMP2) - CEXP);
                float e1 = exp2f(fmaxf(a[1], CLAMP2) - CEXP);
                float e2 = exp2f(fmaxf(a[2], CLAMP2) - CEXP);
                float e3 = exp2f(fmaxf(a[3], CLAMP2) - CEXP);
                zsum[mi*2]   += e0 + e1;
                zsum[mi*2+1] += e2 + e3;
                if (isDiag) {
                    int cb = tt * BN + nj * 8 + colBase;
                    if (cb     == dc[mi*2])   zcorr[mi*2]   += e0;
                    if (cb + 1 == dc[mi*2])   zcorr[mi*2]   += e1;
                    if (cb     == dc[mi*2+1]) zcorr[mi*2+1] += e2;
                    if (cb + 1 == dc[mi*2+1]) zcorr[mi*2+1] += e3;
                }
            }
        }

        // stash for deferred epilogue
        #pragma unroll
        for (int mi = 0; mi < 2; mi++)
            #pragma unroll
            for (int nj = 0; nj < 2; nj++)
                #pragma unroll
                for (int q = 0; q < 4; q++) accPrev[mi][nj][q] = acc[mi][nj][q];

        if (t + 1 < NTILES) {
            CP_WAIT0();
            __syncthreads();
        }
    }

    // tail epilogue: tile NTILES-1
    {
        const int tt = NTILES - 1;
        const bool isDiag = (tt == td);
        #pragma unroll
        for (int g = 0; g < 4; g++) {
            const int mi = g >> 1, nj = g & 1;
            const float* a = accPrev[mi][nj];
            float e0 = exp2f(fmaxf(a[0], CLAMP2) - CEXP);
            float e1 = exp2f(fmaxf(a[1], CLAMP2) - CEXP);
            float e2 = exp2f(fmaxf(a[2], CLAMP2) - CEXP);
            float e3 = exp2f(fmaxf(a[3], CLAMP2) - CEXP);
            zsum[mi*2]   += e0 + e1;
            zsum[mi*2+1] += e2 + e3;
            if (isDiag) {
                int cb = tt * BN + nj * 8 + colBase;
                if (cb     == dc[mi*2])   zcorr[mi*2]   += e0;
                if (cb + 1 == dc[mi*2])   zcorr[mi*2]   += e1;
                if (cb     == dc[mi*2+1]) zcorr[mi*2+1] += e2;
                if (cb + 1 == dc[mi*2+1]) zcorr[mi*2+1] += e3;
            }
        }
    }

    // reduce z across the 4 lanes of each quad (same row)
    #pragma unroll
    for (int sl = 0; sl < 4; sl++) {
        float z = zsum[sl], c = zcorr[sl];
        z += __shfl_xor_sync(0xffffffffu, z, 1);
        z += __shfl_xor_sync(0xffffffffu, z, 2);
        c += __shfl_xor_sync(0xffffffffu, c, 1);
        c += __shfl_xor_sync(0xffffffffu, c, 2);
        if ((lane & 3) == 0) { zbuf[rl[sl]][wn] = z; cbuf[rl[sl]][wn] = c; }
    }
    __syncthreads();

    // per-row loss + block reduce + single atomicAdd
    float loss = 0.f;
    if (tid < BM) {
        int row = br0 + tid;
        float lbl = g_lbl[row];
        float Z = (zbuf[tid][0] + zbuf[tid][1] + zbuf[tid][2] + zbuf[tid][3])
                - (cbuf[tid][0] + cbuf[tid][1] + cbuf[tid][2] + cbuf[tid][3])
                + exp2f(lbl * LOG2E - CEXP);
        loss = 30.f + logf(Z) - lbl;
    }
    #pragma unroll
    for (int off = 16; off > 0; off >>= 1)
        loss += __shfl_xor_sync(0xffffffffu, loss, off);
    if (lane == 0) red[wid] = loss;
    __syncthreads();
    if (tid == 0) {
        float tot = 0.f;
        #pragma unroll
        for (int q = 0; q < 16; q++) tot += red[q];
        atomicAdd(out, tot * (1.f / (float)NR));
    }
}

// ---------------------------------------------------------------------------
extern "C" void kernel_launch(void* const* d_in, const int* in_sizes, int n_in,
                              void* d_out, int out_size) {
    const float* x = (const float*)d_in[0];
    float* out = (float*)d_out;

    prep_kernel<<<NS, 128>>>(x, out);

    cudaFuncSetAttribute(gemm_kernel, cudaFuncAttributeMaxDynamicSharedMemorySize, SM_TOTAL);
    gemm_kernel<<<NR / BM, NT, SM_TOTAL>>>(out);
}